// round 12
// baseline (speedup 1.0000x reference)
#include <cuda_runtime.h>
#include <cstddef>

// TensorProduct: out[n,p,n3,f] with parity coupling through CG[9,9,25].
//  - one thread = one (node, channel-pair); packed fp32x2 (FFMA2)
//  - parity butterfly: U = s1*s2, V = d1*d2; even = U+V, odd = U-V
//  - CG triangle sparsity fully unrolled; CG stored in smem COMPACTED per
//    (i,j) row (nonzero range only), values duplicated into both 32-bit
//    halves of a u64, rows 16B-aligned, so ONE broadcast LDS.128 delivers
//    TWO ready-to-use f32x2 coefficients feeding FOUR FFMA2 ops.

using u64 = unsigned long long;

__device__ __forceinline__ u64 f2mul(u64 a, u64 b) {
    u64 d;
    asm("mul.rn.f32x2 %0, %1, %2;" : "=l"(d) : "l"(a), "l"(b));
    return d;
}
__device__ __forceinline__ u64 f2add(u64 a, u64 b) {
    u64 d;
    asm("add.rn.f32x2 %0, %1, %2;" : "=l"(d) : "l"(a), "l"(b));
    return d;
}
__device__ __forceinline__ u64 f2fma(u64 a, u64 b, u64 c) {
    u64 d;
    asm("fma.rn.f32x2 %0, %1, %2, %3;" : "=l"(d) : "l"(a), "l"(b), "l"(c));
    return d;
}

#define PK_HALF    0x3F0000003F000000ull  // {0.5f, 0.5f}
#define PK_NEGHALF 0xBF000000BF000000ull  // {-0.5f, -0.5f}
#define PK_NEG1    0xBF800000BF800000ull  // {-1.f, -1.f}

static constexpr int LA = 9;
static constexpr int LB = 9;
static constexpr int LC = 25;
static constexpr int FPAIR = 64;
static constexpr int NODES_PER_BLOCK = 2;
static constexpr int THREADS = NODES_PER_BLOCK * FPAIR; // 128

// l quantum number of flattened slot
__host__ __device__ constexpr int lval(int idx) { return idx == 0 ? 0 : (idx < 4 ? 1 : 2); }

// length of the nonzero n3 range for CG row r = i*9+j
__host__ __device__ constexpr int row_len(int r) {
    const int la = lval(r / 9), lb = lval(r % 9);
    const int lo = la > lb ? la - lb : lb - la;
    const int hi = la + lb;
    return (hi + 1) * (hi + 1) - lo * lo;
}
// compacted offset of row r (rows padded to even #u64 => 16B aligned).
// Called with compile-time-constant r inside fully-unrolled loops -> folds.
__host__ __device__ constexpr int cg_off(int r) {
    int o = 0;
    for (int k = 0; k < r; ++k) o += (row_len(k) + 1) & ~1;
    return o;
}
static constexpr int SCG_SLOTS = 1306; // == cg_off(81)
static_assert(cg_off(81) == SCG_SLOTS, "layout size");

__global__ __launch_bounds__(THREADS)
void tp_f32x2_kernel(const float* __restrict__ x1,
                     const float* __restrict__ x2,
                     const float* __restrict__ cg,
                     float* __restrict__ out,
                     int n_nodes)
{
    __shared__ __align__(16) u64 scg[SCG_SLOTS]; // 10.4 KB, duplicated halves

    // ---- loader: one compacted row per thread (81 rows <= 128 threads) ----
    {
        const unsigned* cgu = reinterpret_cast<const unsigned*>(cg);
        const int r = threadIdx.x;
        if (r < 81) {
            const int la = lval(r / 9), lb = lval(r % 9);
            const int lo = la > lb ? la - lb : lb - la;
            const int n30 = lo * lo;
            const int len = row_len(r);
            int base = 0;
            for (int k = 0; k < r; ++k) base += (row_len(k) + 1) & ~1;
            for (int k = 0; k < len; ++k) {
                u64 v = (u64)cgu[r * LC + n30 + k];
                scg[base + k] = (v << 32) | v;
            }
        }
    }
    __syncthreads();

    const int node = blockIdx.x * NODES_PER_BLOCK + (threadIdx.x >> 6);
    const int c    = threadIdx.x & (FPAIR - 1);
    if (node >= n_nodes) return;

    const u64* x1u = reinterpret_cast<const u64*>(x1);
    const u64* x2u = reinterpret_cast<const u64*>(x2);
    u64*       ou  = reinterpret_cast<u64*>(out);

    // ---- load + parity butterfly ----
    u64 s1[LA], d1[LA], s2[LB], d2[LB];

    const u64* p0 = x1u + ((size_t)node * 2 * LA) * FPAIR + c;
    #pragma unroll
    for (int l = 0; l < LA; ++l) {
        u64 a0 = p0[l * FPAIR];
        u64 a1 = p0[(LA + l) * FPAIR];
        u64 h  = f2mul(a0, PK_HALF);
        s1[l]  = f2fma(a1, PK_HALF,    h);  // 0.5*(a0+a1)
        d1[l]  = f2fma(a1, PK_NEGHALF, h);  // 0.5*(a0-a1)
    }

    const u64* q0 = x2u + ((size_t)node * 2 * LB) * FPAIR + c;
    #pragma unroll
    for (int m = 0; m < LB; ++m) {
        u64 b0 = q0[m * FPAIR];
        u64 b1 = q0[(LB + m) * FPAIR];
        s2[m]  = f2add(b0, b1);             // (b0+b1)
        d2[m]  = f2fma(b1, PK_NEG1, b0);    // (b0-b1)
    }
    // s1*s2 + d1*d2 = even;  s1*s2 - d1*d2 = odd

    // ---- accumulate U,V streams against compacted CG ----
    u64 accU[LC], accV[LC];
    #pragma unroll
    for (int k = 0; k < LC; ++k) { accU[k] = 0ull; accV[k] = 0ull; }

    #pragma unroll
    for (int i = 0; i < LA; ++i) {
        const int la = lval(i);
        #pragma unroll
        for (int j = 0; j < LB; ++j) {
            const int lb  = lval(j);
            const int lo  = (la > lb) ? (la - lb) : (lb - la);
            const int hi  = la + lb;
            const int n30 = lo * lo;
            const int len = (hi + 1) * (hi + 1) - n30;  // compile-time, odd
            const int np  = len >> 1;
            const int base = cg_off(i * LB + j);        // compile-time

            const u64 U = f2mul(s1[i], s2[j]);
            const u64 V = f2mul(d1[i], d2[j]);

            // pairs: one LDS.128 -> two duplicated coeffs -> 4 FFMA2
            #pragma unroll
            for (int p = 0; p < np; ++p) {
                const ulonglong2 cc =
                    *reinterpret_cast<const ulonglong2*>(&scg[base + 2 * p]);
                const int n3 = n30 + 2 * p;
                accU[n3]     = f2fma(cc.x, U, accU[n3]);
                accV[n3]     = f2fma(cc.x, V, accV[n3]);
                accU[n3 + 1] = f2fma(cc.y, U, accU[n3 + 1]);
                accV[n3 + 1] = f2fma(cc.y, V, accV[n3 + 1]);
            }
            // odd tail (every row, compile-time)
            {
                const u64 ct = scg[base + len - 1];
                const int n3 = n30 + len - 1;
                accU[n3] = f2fma(ct, U, accU[n3]);
                accV[n3] = f2fma(ct, V, accV[n3]);
            }
        }
    }

    // ---- butterfly back to parities and store ----
    u64* o0 = ou + ((size_t)node * 2 * LC) * FPAIR + c;
    #pragma unroll
    for (int k = 0; k < LC; ++k) {
        o0[k * FPAIR]        = f2add(accU[k], accV[k]);           // even
        o0[(LC + k) * FPAIR] = f2fma(accV[k], PK_NEG1, accU[k]);  // odd
    }
}

extern "C" void kernel_launch(void* const* d_in, const int* in_sizes, int n_in,
                              void* d_out, int out_size)
{
    const float* x1 = (const float*)d_in[0]; // [N, 2, 9, 128]
    const float* x2 = (const float*)d_in[1]; // [N, 2, 9, 128]
    const float* cg = (const float*)d_in[2]; // [9, 9, 25]
    float* out = (float*)d_out;              // [N, 2, 25, 128]

    const int n_nodes = in_sizes[0] / (2 * LA * 128);
    const int grid = (n_nodes + NODES_PER_BLOCK - 1) / NODES_PER_BLOCK;

    tp_f32x2_kernel<<<grid, THREADS>>>(x1, x2, cg, out, n_nodes);
}